// round 1
// baseline (speedup 1.0000x reference)
#include <cuda_runtime.h>
#include <cstdint>

#define NMAX 50048
#define HD   128
#define GG   16

// Scratch (no cudaMalloc allowed): 3 node-feature buffers + pooling accumulators
__device__ float g_A[NMAX * HD];
__device__ float g_B[NMAX * HD];
__device__ float g_C[NMAX * HD];
__device__ float g_sums[GG * HD];
__device__ float g_cnt[GG];

// ---------------------------------------------------------------- copy h -> Z
__global__ void copy_kernel(const float* __restrict__ in, float* __restrict__ out, int n4) {
    int i = blockIdx.x * blockDim.x + threadIdx.x;
    if (i < n4) ((float4*)out)[i] = ((const float4*)in)[i];
}

// ------------------------------------------------- edge scatter: Z[dst] += H[src]
// one warp per edge; lane handles 4 contiguous floats (float4 gather, 4 scalar atomics)
__global__ void edge_kernel(const float* __restrict__ H, const int* __restrict__ src,
                            const int* __restrict__ dst, float* __restrict__ Z, int nE) {
    long long gtid = (long long)blockIdx.x * blockDim.x + threadIdx.x;
    int e = (int)(gtid >> 5);
    if (e >= nE) return;
    int lane = threadIdx.x & 31;
    int s = __ldg(src + e);
    int d = __ldg(dst + e);
    float4 v = ((const float4*)H)[(size_t)s * 32 + lane];
    float* p = Z + (size_t)d * HD + lane * 4;
    atomicAdd(p + 0, v.x);
    atomicAdd(p + 1, v.y);
    atomicAdd(p + 2, v.z);
    atomicAdd(p + 3, v.w);
}

// ------------------------------------------------- fused GEMM + bias + relu
// O = relu(Z @ W + b), optional duplicate write to O2 (seeds next layer's z buffer).
// Block: 256 threads = 8 warps. Block tile: 64 rows x 128 cols, K = 128.
// W (64KB) + Z tile (32KB) staged in dynamic smem. Warp w owns rows [w*8, w*8+8),
// lane owns 4 contiguous cols -> all z smem loads are warp-uniform broadcasts,
// all W smem loads are conflict-free float4.
__global__ void __launch_bounds__(256) gemm_kernel(
    const float* __restrict__ Z, const float* __restrict__ W,
    const float* __restrict__ bias, float* __restrict__ O1,
    float* __restrict__ O2, int nrows)
{
    extern __shared__ float smem[];
    float* sW = smem;                 // 128*128
    float* sZ = smem + HD * HD;       // 64*128
    float* sB = sZ + 64 * HD;         // 128
    int tid = threadIdx.x;

    // stage W
    float4* sW4 = (float4*)sW;
    const float4* W4 = (const float4*)W;
    #pragma unroll
    for (int i = tid; i < HD * HD / 4; i += 256) sW4[i] = W4[i];
    if (tid < HD) sB[tid] = bias[tid];

    // stage Z tile (zero-fill past nrows)
    int row0 = blockIdx.x * 64;
    float4* sZ4 = (float4*)sZ;
    const float4* Z4 = (const float4*)Z;
    for (int i = tid; i < 64 * HD / 4; i += 256) {
        int r = i >> 5;
        float4 v = make_float4(0.f, 0.f, 0.f, 0.f);
        if (row0 + r < nrows) v = Z4[(size_t)(row0 + r) * 32 + (i & 31)];
        sZ4[i] = v;
    }
    __syncthreads();

    int warp = tid >> 5;
    int lane = tid & 31;
    int c0 = lane * 4;

    float acc[8][4];
    #pragma unroll
    for (int r = 0; r < 8; r++) {
        acc[r][0] = 0.f; acc[r][1] = 0.f; acc[r][2] = 0.f; acc[r][3] = 0.f;
    }

    const float* zb = sZ + warp * 8 * HD;
    #pragma unroll 4
    for (int k = 0; k < HD; k += 4) {
        float4 zr[8];
        #pragma unroll
        for (int r = 0; r < 8; r++) zr[r] = *(const float4*)(zb + r * HD + k);
        #pragma unroll
        for (int kk = 0; kk < 4; kk++) {
            float4 w = *(const float4*)(sW + (k + kk) * HD + c0);
            #pragma unroll
            for (int r = 0; r < 8; r++) {
                float zv = (kk == 0) ? zr[r].x : (kk == 1) ? zr[r].y
                          : (kk == 2) ? zr[r].z : zr[r].w;
                acc[r][0] += zv * w.x;
                acc[r][1] += zv * w.y;
                acc[r][2] += zv * w.z;
                acc[r][3] += zv * w.w;
            }
        }
    }

    #pragma unroll
    for (int r = 0; r < 8; r++) {
        int row = row0 + warp * 8 + r;
        if (row < nrows) {
            float4 o;
            o.x = fmaxf(acc[r][0] + sB[c0 + 0], 0.f);
            o.y = fmaxf(acc[r][1] + sB[c0 + 1], 0.f);
            o.z = fmaxf(acc[r][2] + sB[c0 + 2], 0.f);
            o.w = fmaxf(acc[r][3] + sB[c0 + 3], 0.f);
            ((float4*)O1)[(size_t)row * 32 + lane] = o;
            if (O2) ((float4*)O2)[(size_t)row * 32 + lane] = o;
        }
    }
}

// ---------------------------------------------------------------- pooling
__global__ void zero_kernel() {
    int i = threadIdx.x;
    for (int j = i; j < GG * HD; j += 256) g_sums[j] = 0.f;
    if (i < GG) g_cnt[i] = 0.f;
}

__global__ void pool_kernel(const float* __restrict__ Hf, const int* __restrict__ gid,
                            int nrows) {
    __shared__ float s[GG * HD];
    __shared__ float sc[GG];
    int tid = threadIdx.x;  // 128
    for (int i = tid; i < GG * HD; i += 128) s[i] = 0.f;
    if (tid < GG) sc[tid] = 0.f;
    __syncthreads();
    int start = blockIdx.x * 128;
    int end = min(start + 128, nrows);
    for (int r = start; r < end; r++) {
        int g = __ldg(gid + r);  // warp-uniform broadcast
        s[(g << 7) + tid] += Hf[(size_t)r * HD + tid];
        if (tid == 0) sc[g] += 1.f;
    }
    __syncthreads();
    for (int i = tid; i < GG * HD; i += 128) atomicAdd(&g_sums[i], s[i]);
    if (tid < GG) atomicAdd(&g_cnt[tid], sc[tid]);
}

// ---------------------------------------------------------------- classifier
__global__ void cls_kernel(const float* __restrict__ Wc1, const float* __restrict__ bc1,
                           const float* __restrict__ Wc2, const float* __restrict__ bc2,
                           float* __restrict__ out) {
    __shared__ float hg[GG * HD];
    __shared__ float t1[GG * HD];
    int tid = threadIdx.x;  // 256
    for (int i = tid; i < GG * HD; i += 256) {
        int g = i >> 7;
        hg[i] = g_sums[i] / fmaxf(g_cnt[g], 1.f);
    }
    __syncthreads();
    for (int i = tid; i < GG * HD; i += 256) {
        int g = i >> 7, c = i & 127;
        float a = bc1[c];
        #pragma unroll 8
        for (int k = 0; k < HD; k++) a += hg[(g << 7) + k] * Wc1[k * HD + c];
        t1[i] = fmaxf(a, 0.f);
    }
    __syncthreads();
    for (int i = tid; i < GG * 10; i += 256) {
        int g = i / 10, c = i - g * 10;
        float a = bc2[c];
        #pragma unroll 8
        for (int k = 0; k < HD; k++) a += t1[(g << 7) + k] * Wc2[k * 10 + c];
        out[i] = a;
    }
}

// ---------------------------------------------------------------- launch
extern "C" void kernel_launch(void* const* d_in, const int* in_sizes, int n_in,
                              void* d_out, int out_size) {
    const float* h   = (const float*)d_in[0];
    const int*   src = (const int*)d_in[1];
    const int*   dst = (const int*)d_in[2];
    const int*   gid = (const int*)d_in[3];
    const float* W1a = (const float*)d_in[4];  const float* b1a = (const float*)d_in[5];
    const float* W2a = (const float*)d_in[6];  const float* b2a = (const float*)d_in[7];
    const float* W1b = (const float*)d_in[8];  const float* b1b = (const float*)d_in[9];
    const float* W2b = (const float*)d_in[10]; const float* b2b = (const float*)d_in[11];
    const float* Wc1 = (const float*)d_in[12]; const float* bc1 = (const float*)d_in[13];
    const float* Wc2 = (const float*)d_in[14]; const float* bc2 = (const float*)d_in[15];
    float* out = (float*)d_out;

    int N = in_sizes[0] / HD;
    int E = in_sizes[1];

    float *A, *B, *C;
    cudaGetSymbolAddress((void**)&A, g_A);
    cudaGetSymbolAddress((void**)&B, g_B);
    cudaGetSymbolAddress((void**)&C, g_C);

    const int SMEM = (HD * HD + 64 * HD + HD) * sizeof(float);  // 98816 B
    cudaFuncSetAttribute(gemm_kernel, cudaFuncAttributeMaxDynamicSharedMemorySize, SMEM);

    int n4 = N * (HD / 4);
    int edge_blocks = (int)(((long long)E * 32 + 255) / 256);
    int gb = (N + 63) / 64;

    // Layer A
    copy_kernel<<<(n4 + 255) / 256, 256>>>(h, A, n4);             // A = h
    edge_kernel<<<edge_blocks, 256>>>(h, src, dst, A, E);         // A = z1
    gemm_kernel<<<gb, 256, SMEM>>>(A, W1a, b1a, B, nullptr, N);   // B = relu(z1 W1a+b)
    gemm_kernel<<<gb, 256, SMEM>>>(B, W2a, b2a, A, C, N);         // A = h1, C = h1 (z2 seed)
    // Layer B
    edge_kernel<<<edge_blocks, 256>>>(A, src, dst, C, E);         // C = z2
    gemm_kernel<<<gb, 256, SMEM>>>(C, W1b, b1b, B, nullptr, N);
    gemm_kernel<<<gb, 256, SMEM>>>(B, W2b, b2b, A, nullptr, N);   // A = h2
    // Readout + classifier
    zero_kernel<<<1, 256>>>();
    pool_kernel<<<(N + 127) / 128, 128>>>(A, gid, N);
    cls_kernel<<<1, 256>>>(Wc1, bc1, Wc2, bc2, out);
}

// round 2
// speedup vs baseline: 1.9596x; 1.9596x over previous
#include <cuda_runtime.h>
#include <cstdint>

#define NMAX 50048
#define EMAX 800000
#define HD   128
#define GG   16

// Scratch (no cudaMalloc allowed)
__device__ float g_A[NMAX * HD];
__device__ float g_B[NMAX * HD];
__device__ float g_C[NMAX * HD];
__device__ float g_sums[GG * HD];
__device__ float g_cnt[GG];
__device__ int   g_rowptr[NMAX + 1];
__device__ int   g_cursor[NMAX];
__device__ int   g_csr[EMAX];

// ---------------------------------------------------------------- CSR build
__global__ void zero_counts_kernel(int n) {
    int i = blockIdx.x * blockDim.x + threadIdx.x;
    if (i < n) g_cursor[i] = 0;
}

__global__ void hist_kernel(const int* __restrict__ dst, int nE) {
    int e = blockIdx.x * blockDim.x + threadIdx.x;
    if (e < nE) atomicAdd(&g_cursor[dst[e]], 1);
}

// single-block inclusive scan over counts -> rowptr[1..N]; rowptr[0]=0
__global__ void scan_kernel(int n) {
    __shared__ int warpsums[32];
    int tid = threadIdx.x;             // 1024 threads
    int lane = tid & 31, w = tid >> 5;
    int carry = 0;
    for (int base = 0; base < n; base += 1024) {
        int i = base + tid;
        int v = (i < n) ? g_cursor[i] : 0;
        // warp inclusive scan
        int x = v;
        #pragma unroll
        for (int o = 1; o < 32; o <<= 1) {
            int y = __shfl_up_sync(0xFFFFFFFFu, x, o);
            if (lane >= o) x += y;
        }
        if (lane == 31) warpsums[w] = x;
        __syncthreads();
        if (w == 0) {
            int y = warpsums[lane];
            #pragma unroll
            for (int o = 1; o < 32; o <<= 1) {
                int z = __shfl_up_sync(0xFFFFFFFFu, y, o);
                if (lane >= o) y += z;
            }
            warpsums[lane] = y;
        }
        __syncthreads();
        int incl = x + (w > 0 ? warpsums[w - 1] : 0) + carry;
        if (i < n) g_rowptr[i + 1] = incl;
        int total = warpsums[31];
        __syncthreads();               // protect warpsums before next iter
        carry += total;
    }
    if (tid == 0) g_rowptr[0] = 0;
}

__global__ void seed_cursor_kernel(int n) {
    int i = blockIdx.x * blockDim.x + threadIdx.x;
    if (i < n) g_cursor[i] = g_rowptr[i];
}

__global__ void fill_kernel(const int* __restrict__ src, const int* __restrict__ dst, int nE) {
    int e = blockIdx.x * blockDim.x + threadIdx.x;
    if (e < nE) {
        int pos = atomicAdd(&g_cursor[dst[e]], 1);
        g_csr[pos] = src[e];
    }
}

// ------------------------------------------------- CSR gather aggregation
// one warp per node: Z[i] = H[i] + sum_{e in row i} H[csr[e]]
__global__ void __launch_bounds__(256) agg_kernel(const float* __restrict__ H,
                                                  float* __restrict__ Z, int nrows) {
    int warp = threadIdx.x >> 5;
    int lane = threadIdx.x & 31;
    int node = blockIdx.x * 8 + warp;
    if (node >= nrows) return;
    const float4* H4 = (const float4*)H;
    float4 acc = H4[(size_t)node * 32 + lane];
    int beg = g_rowptr[node];
    int end = g_rowptr[node + 1];
    for (int e = beg; e < end; e++) {
        int s = g_csr[e];              // warp-uniform broadcast
        float4 v = H4[(size_t)s * 32 + lane];
        acc.x += v.x; acc.y += v.y; acc.z += v.z; acc.w += v.w;
    }
    ((float4*)Z)[(size_t)node * 32 + lane] = acc;
}

// ------------------------------------------------- fused GEMM + bias + relu
__global__ void __launch_bounds__(256) gemm_kernel(
    const float* __restrict__ Z, const float* __restrict__ W,
    const float* __restrict__ bias, float* __restrict__ O1, int nrows)
{
    extern __shared__ float smem[];
    float* sW = smem;                 // 128*128
    float* sZ = smem + HD * HD;       // 64*128
    float* sB = sZ + 64 * HD;         // 128
    int tid = threadIdx.x;

    float4* sW4 = (float4*)sW;
    const float4* W4 = (const float4*)W;
    #pragma unroll
    for (int i = tid; i < HD * HD / 4; i += 256) sW4[i] = W4[i];
    if (tid < HD) sB[tid] = bias[tid];

    int row0 = blockIdx.x * 64;
    float4* sZ4 = (float4*)sZ;
    const float4* Z4 = (const float4*)Z;
    for (int i = tid; i < 64 * HD / 4; i += 256) {
        int r = i >> 5;
        float4 v = make_float4(0.f, 0.f, 0.f, 0.f);
        if (row0 + r < nrows) v = Z4[(size_t)(row0 + r) * 32 + (i & 31)];
        sZ4[i] = v;
    }
    __syncthreads();

    int warp = tid >> 5;
    int lane = tid & 31;
    int c0 = lane * 4;

    float acc[8][4];
    #pragma unroll
    for (int r = 0; r < 8; r++) {
        acc[r][0] = 0.f; acc[r][1] = 0.f; acc[r][2] = 0.f; acc[r][3] = 0.f;
    }

    const float* zb = sZ + warp * 8 * HD;
    #pragma unroll 4
    for (int k = 0; k < HD; k += 4) {
        float4 zr[8];
        #pragma unroll
        for (int r = 0; r < 8; r++) zr[r] = *(const float4*)(zb + r * HD + k);
        #pragma unroll
        for (int kk = 0; kk < 4; kk++) {
            float4 w = *(const float4*)(sW + (k + kk) * HD + c0);
            #pragma unroll
            for (int r = 0; r < 8; r++) {
                float zv = (kk == 0) ? zr[r].x : (kk == 1) ? zr[r].y
                          : (kk == 2) ? zr[r].z : zr[r].w;
                acc[r][0] += zv * w.x;
                acc[r][1] += zv * w.y;
                acc[r][2] += zv * w.z;
                acc[r][3] += zv * w.w;
            }
        }
    }

    #pragma unroll
    for (int r = 0; r < 8; r++) {
        int row = row0 + warp * 8 + r;
        if (row < nrows) {
            float4 o;
            o.x = fmaxf(acc[r][0] + sB[c0 + 0], 0.f);
            o.y = fmaxf(acc[r][1] + sB[c0 + 1], 0.f);
            o.z = fmaxf(acc[r][2] + sB[c0 + 2], 0.f);
            o.w = fmaxf(acc[r][3] + sB[c0 + 3], 0.f);
            ((float4*)O1)[(size_t)row * 32 + lane] = o;
        }
    }
}

// ---------------------------------------------------------------- pooling
__global__ void zero_pool_kernel() {
    int i = threadIdx.x;
    for (int j = i; j < GG * HD; j += 256) g_sums[j] = 0.f;
    if (i < GG) g_cnt[i] = 0.f;
}

__global__ void pool_kernel(const float* __restrict__ Hf, const int* __restrict__ gid,
                            int nrows) {
    __shared__ float s[GG * HD];
    __shared__ float sc[GG];
    int tid = threadIdx.x;  // 128
    for (int i = tid; i < GG * HD; i += 128) s[i] = 0.f;
    if (tid < GG) sc[tid] = 0.f;
    __syncthreads();
    int start = blockIdx.x * 128;
    int end = min(start + 128, nrows);
    for (int r = start; r < end; r++) {
        int g = __ldg(gid + r);
        s[(g << 7) + tid] += Hf[(size_t)r * HD + tid];
        if (tid == 0) sc[g] += 1.f;
    }
    __syncthreads();
    for (int i = tid; i < GG * HD; i += 128) atomicAdd(&g_sums[i], s[i]);
    if (tid < GG) atomicAdd(&g_cnt[tid], sc[tid]);
}

// ---------------------------------------------------------------- classifier
__global__ void cls_kernel(const float* __restrict__ Wc1, const float* __restrict__ bc1,
                           const float* __restrict__ Wc2, const float* __restrict__ bc2,
                           float* __restrict__ out) {
    __shared__ float hg[GG * HD];
    __shared__ float t1[GG * HD];
    int tid = threadIdx.x;  // 256
    for (int i = tid; i < GG * HD; i += 256) {
        int g = i >> 7;
        hg[i] = g_sums[i] / fmaxf(g_cnt[g], 1.f);
    }
    __syncthreads();
    for (int i = tid; i < GG * HD; i += 256) {
        int g = i >> 7, c = i & 127;
        float a = bc1[c];
        #pragma unroll 8
        for (int k = 0; k < HD; k++) a += hg[(g << 7) + k] * Wc1[k * HD + c];
        t1[i] = fmaxf(a, 0.f);
    }
    __syncthreads();
    for (int i = tid; i < GG * 10; i += 256) {
        int g = i / 10, c = i - g * 10;
        float a = bc2[c];
        #pragma unroll 8
        for (int k = 0; k < HD; k++) a += t1[(g << 7) + k] * Wc2[k * 10 + c];
        out[i] = a;
    }
}

// ---------------------------------------------------------------- launch
extern "C" void kernel_launch(void* const* d_in, const int* in_sizes, int n_in,
                              void* d_out, int out_size) {
    const float* h   = (const float*)d_in[0];
    const int*   src = (const int*)d_in[1];
    const int*   dst = (const int*)d_in[2];
    const int*   gid = (const int*)d_in[3];
    const float* W1a = (const float*)d_in[4];  const float* b1a = (const float*)d_in[5];
    const float* W2a = (const float*)d_in[6];  const float* b2a = (const float*)d_in[7];
    const float* W1b = (const float*)d_in[8];  const float* b1b = (const float*)d_in[9];
    const float* W2b = (const float*)d_in[10]; const float* b2b = (const float*)d_in[11];
    const float* Wc1 = (const float*)d_in[12]; const float* bc1 = (const float*)d_in[13];
    const float* Wc2 = (const float*)d_in[14]; const float* bc2 = (const float*)d_in[15];
    float* out = (float*)d_out;

    int N = in_sizes[0] / HD;
    int E = in_sizes[1];

    float *A, *B, *C;
    cudaGetSymbolAddress((void**)&A, g_A);
    cudaGetSymbolAddress((void**)&B, g_B);
    cudaGetSymbolAddress((void**)&C, g_C);

    const int SMEM = (HD * HD + 64 * HD + HD) * sizeof(float);  // 98816 B
    cudaFuncSetAttribute(gemm_kernel, cudaFuncAttributeMaxDynamicSharedMemorySize, SMEM);

    int nb = (N + 255) / 256;
    int eb = (E + 255) / 256;
    int ab = (N + 7) / 8;
    int gb = (N + 63) / 64;

    // Build CSR (by dst) once; reused by both layers
    zero_counts_kernel<<<nb, 256>>>(N);
    hist_kernel<<<eb, 256>>>(dst, E);
    scan_kernel<<<1, 1024>>>(N);
    seed_cursor_kernel<<<nb, 256>>>(N);
    fill_kernel<<<eb, 256>>>(src, dst, E);

    // Layer A
    agg_kernel<<<ab, 256>>>(h, A, N);                       // A = z1 = h + agg(h)
    gemm_kernel<<<gb, 256, SMEM>>>(A, W1a, b1a, B, N);
    gemm_kernel<<<gb, 256, SMEM>>>(B, W2a, b2a, A, N);      // A = h1
    // Layer B
    agg_kernel<<<ab, 256>>>(A, C, N);                       // C = z2
    gemm_kernel<<<gb, 256, SMEM>>>(C, W1b, b1b, B, N);
    gemm_kernel<<<gb, 256, SMEM>>>(B, W2b, b2b, A, N);      // A = h2
    // Readout + classifier
    zero_pool_kernel<<<1, 256>>>();
    pool_kernel<<<(N + 127) / 128, 128>>>(A, gid, N);
    cls_kernel<<<1, 256>>>(Wc1, bc1, Wc2, bc2, out);
}

// round 4
// speedup vs baseline: 2.4375x; 1.2439x over previous
#include <cuda_runtime.h>
#include <cuda_bf16.h>
#include <cstdint>

#define NMAX 50048
#define EMAX 800000
#define HD   128
#define GG   16

// Scratch (no cudaMalloc allowed)
__device__ __align__(16) float g_A[NMAX * HD];
__device__ __align__(16) float g_B[NMAX * HD];
__device__ __align__(16) float g_C[NMAX * HD];
__device__ float g_sums[GG * HD];
__device__ float g_cnt[GG];
__device__ int   g_rowptr[NMAX + 1];
__device__ int   g_cursor[NMAX];
__device__ int   g_csr[EMAX];
// Pre-split weights, n-major [layer][n][k], bf16 hi/lo
__device__ __align__(16) __nv_bfloat16 g_Wbh[4 * 16384];
__device__ __align__(16) __nv_bfloat16 g_Wbl[4 * 16384];

// ================================================================ CSR build
__global__ void zero_counts_kernel(int n) {
    int i = blockIdx.x * blockDim.x + threadIdx.x;
    if (i < n) g_cursor[i] = 0;
}
__global__ void hist_kernel(const int* __restrict__ dst, int nE) {
    int e = blockIdx.x * blockDim.x + threadIdx.x;
    if (e < nE) atomicAdd(&g_cursor[dst[e]], 1);
}
__global__ void scan_kernel(int n) {
    __shared__ int warpsums[32];
    int tid = threadIdx.x, lane = tid & 31, w = tid >> 5;
    int carry = 0;
    for (int base = 0; base < n; base += 1024) {
        int i = base + tid;
        int v = (i < n) ? g_cursor[i] : 0;
        int x = v;
        #pragma unroll
        for (int o = 1; o < 32; o <<= 1) {
            int y = __shfl_up_sync(0xFFFFFFFFu, x, o);
            if (lane >= o) x += y;
        }
        if (lane == 31) warpsums[w] = x;
        __syncthreads();
        if (w == 0) {
            int y = warpsums[lane];
            #pragma unroll
            for (int o = 1; o < 32; o <<= 1) {
                int z = __shfl_up_sync(0xFFFFFFFFu, y, o);
                if (lane >= o) y += z;
            }
            warpsums[lane] = y;
        }
        __syncthreads();
        int incl = x + (w > 0 ? warpsums[w - 1] : 0) + carry;
        if (i < n) g_rowptr[i + 1] = incl;
        int total = warpsums[31];
        __syncthreads();
        carry += total;
    }
    if (tid == 0) g_rowptr[0] = 0;
}
__global__ void seed_cursor_kernel(int n) {
    int i = blockIdx.x * blockDim.x + threadIdx.x;
    if (i < n) g_cursor[i] = g_rowptr[i];
}
__global__ void fill_kernel(const int* __restrict__ src, const int* __restrict__ dst, int nE) {
    int e = blockIdx.x * blockDim.x + threadIdx.x;
    if (e < nE) {
        int pos = atomicAdd(&g_cursor[dst[e]], 1);
        g_csr[pos] = src[e];
    }
}

// ------------------------------------------------- CSR gather aggregation
__global__ void __launch_bounds__(256) agg_kernel(const float* __restrict__ H,
                                                  float* __restrict__ Z, int nrows) {
    int warp = threadIdx.x >> 5;
    int lane = threadIdx.x & 31;
    int node = blockIdx.x * 8 + warp;
    if (node >= nrows) return;
    const float4* H4 = (const float4*)H;
    float4 acc = H4[(size_t)node * 32 + lane];
    int beg = g_rowptr[node];
    int end = g_rowptr[node + 1];
    for (int e = beg; e < end; e++) {
        int s = g_csr[e];
        float4 v = H4[(size_t)s * 32 + lane];
        acc.x += v.x; acc.y += v.y; acc.z += v.z; acc.w += v.w;
    }
    ((float4*)Z)[(size_t)node * 32 + lane] = acc;
}

// ================================================================ W pre-split
// W[k][n] row-major -> n-major bf16 hi/lo: g_Wb*[layer][n*128 + k]
__global__ void wsplit_kernel(const float* __restrict__ W1a, const float* __restrict__ W2a,
                              const float* __restrict__ W1b, const float* __restrict__ W2b) {
    int idx = blockIdx.x * 256 + threadIdx.x;
    if (idx >= 4 * 16384) return;
    int w = idx >> 14, rem = idx & 16383;
    int n = rem >> 7, k = rem & 127;
    const float* Wp = (w == 0) ? W1a : (w == 1) ? W2a : (w == 2) ? W1b : W2b;
    float v = Wp[k * 128 + n];
    __nv_bfloat16 hi = __float2bfloat16(v);
    __nv_bfloat16 lo = __float2bfloat16(v - __bfloat162float(hi));
    g_Wbh[idx] = hi;
    g_Wbl[idx] = lo;
}

// ================================================================ mma.sync GEMM
// O = relu(Z @ W + b). CTA tile 128x128, K=128. bf16 hi/lo split (3 products).
// smem rows padded to 272B -> fragment loads conflict-free (bank = 4*row+quad).
#define APITCH 136          // bf16 elements per padded row (272 B)
#define OFF_AH 0
#define OFF_AL 34816
#define OFF_BH 69632
#define OFF_BL 104448
#define OFF_BIAS 139264
#define SMEM_MMA (139264 + 512)

#define MMA16816(d, a, b0, b1) \
    asm volatile("mma.sync.aligned.m16n8k16.row.col.f32.bf16.bf16.f32 " \
        "{%0,%1,%2,%3}, {%4,%5,%6,%7}, {%8,%9}, {%0,%1,%2,%3};" \
        : "+f"((d)[0]), "+f"((d)[1]), "+f"((d)[2]), "+f"((d)[3]) \
        : "r"((a)[0]), "r"((a)[1]), "r"((a)[2]), "r"((a)[3]), "r"(b0), "r"(b1))

__global__ void __launch_bounds__(256) gemm_mma_kernel(
    const float* __restrict__ Z, const __nv_bfloat16* __restrict__ Wh,
    const __nv_bfloat16* __restrict__ Wl, const float* __restrict__ bias,
    float* __restrict__ O, int nrows)
{
    extern __shared__ char smem[];
    int tid = threadIdx.x, wid = tid >> 5, lane = tid & 31;
    int row0 = blockIdx.x * 128;

    // ---- stage B (copy with repad, 16B chunks) + bias
    {
        const uint4* Bh4 = (const uint4*)Wh;   // 2048 uint4 = 128 rows x 16 chunks
        const uint4* Bl4 = (const uint4*)Wl;
        #pragma unroll
        for (int i = tid; i < 2048; i += 256) {
            int r = i >> 4, c = i & 15;
            *(uint4*)(smem + OFF_BH + r * 272 + c * 16) = Bh4[i];
            *(uint4*)(smem + OFF_BL + r * 272 + c * 16) = Bl4[i];
        }
        if (tid < 128) ((float*)(smem + OFF_BIAS))[tid] = bias[tid];
    }
    // ---- stage A: convert fp32 -> bf16 hi/lo. thread t: row t>>1, half t&1 (64 floats)
    {
        int r = tid >> 1, hhalf = tid & 1;
        int row = row0 + r;
        const float4* Zr = (const float4*)(Z + (size_t)row * HD) + hhalf * 16;
        uint32_t* dh = (uint32_t*)(smem + OFF_AH + r * 272 + hhalf * 128);
        uint32_t* dl = (uint32_t*)(smem + OFF_AL + r * 272 + hhalf * 128);
        bool ok = (row < nrows);
        #pragma unroll
        for (int j = 0; j < 16; j++) {
            float4 v = ok ? Zr[j] : make_float4(0.f, 0.f, 0.f, 0.f);
            __nv_bfloat16 hx = __float2bfloat16(v.x), hy = __float2bfloat16(v.y);
            __nv_bfloat16 hz = __float2bfloat16(v.z), hw = __float2bfloat16(v.w);
            __nv_bfloat162 h0 = __nv_bfloat162(hx, hy), h1 = __nv_bfloat162(hz, hw);
            __nv_bfloat162 l0 = __nv_bfloat162(
                __float2bfloat16(v.x - __bfloat162float(hx)),
                __float2bfloat16(v.y - __bfloat162float(hy)));
            __nv_bfloat162 l1 = __nv_bfloat162(
                __float2bfloat16(v.z - __bfloat162float(hz)),
                __float2bfloat16(v.w - __bfloat162float(hw)));
            dh[j * 2 + 0] = *(uint32_t*)&h0;
            dh[j * 2 + 1] = *(uint32_t*)&h1;
            dl[j * 2 + 0] = *(uint32_t*)&l0;
            dl[j * 2 + 1] = *(uint32_t*)&l1;
        }
    }
    __syncthreads();

    // ---- mainloop: warp (wm = wid>>1, wn = wid&1) owns 32 rows x 64 cols
    int wm = wid >> 1, wn = wid & 1;
    int qrow = lane >> 2;            // 0..7
    int qk = (lane & 3) * 2;         // 0,2,4,6

    float acc[16][4];
    #pragma unroll
    for (int i = 0; i < 16; i++) {
        acc[i][0] = 0.f; acc[i][1] = 0.f; acc[i][2] = 0.f; acc[i][3] = 0.f;
    }

    const char* aH = smem + OFF_AH + (size_t)(wm * 32 + qrow) * 272;
    const char* aL = smem + OFF_AL + (size_t)(wm * 32 + qrow) * 272;
    const char* bH = smem + OFF_BH + (size_t)(wn * 64 + qrow) * 272;
    const char* bL = smem + OFF_BL + (size_t)(wn * 64 + qrow) * 272;

    #pragma unroll
    for (int kt = 0; kt < 8; kt++) {
        int kb = (kt * 16 + qk) * 2;   // byte offset within row
        uint32_t ah[2][4], al[2][4];
        #pragma unroll
        for (int mt = 0; mt < 2; mt++) {
            const char* pH = aH + mt * 16 * 272;
            const char* pL = aL + mt * 16 * 272;
            ah[mt][0] = *(const uint32_t*)(pH + kb);
            ah[mt][1] = *(const uint32_t*)(pH + 8 * 272 + kb);
            ah[mt][2] = *(const uint32_t*)(pH + kb + 16);
            ah[mt][3] = *(const uint32_t*)(pH + 8 * 272 + kb + 16);
            al[mt][0] = *(const uint32_t*)(pL + kb);
            al[mt][1] = *(const uint32_t*)(pL + 8 * 272 + kb);
            al[mt][2] = *(const uint32_t*)(pL + kb + 16);
            al[mt][3] = *(const uint32_t*)(pL + 8 * 272 + kb + 16);
        }
        #pragma unroll
        for (int nt = 0; nt < 8; nt++) {
            const char* pBh = bH + nt * 8 * 272;
            const char* pBl = bL + nt * 8 * 272;
            uint32_t bh0 = *(const uint32_t*)(pBh + kb);
            uint32_t bh1 = *(const uint32_t*)(pBh + kb + 16);
            uint32_t bl0 = *(const uint32_t*)(pBl + kb);
            uint32_t bl1 = *(const uint32_t*)(pBl + kb + 16);
            #pragma unroll
            for (int mt = 0; mt < 2; mt++) {
                MMA16816(acc[mt * 8 + nt], ah[mt], bh0, bh1);
                MMA16816(acc[mt * 8 + nt], al[mt], bh0, bh1);
                MMA16816(acc[mt * 8 + nt], ah[mt], bl0, bl1);
            }
        }
    }

    // ---- epilogue: bias + relu, float2 stores
    const float* sBias = (const float*)(smem + OFF_BIAS);
    #pragma unroll
    for (int mt = 0; mt < 2; mt++) {
        #pragma unroll
        for (int nt = 0; nt < 8; nt++) {
            int row = row0 + wm * 32 + mt * 16 + qrow;
            int col = wn * 64 + nt * 8 + qk;
            float* a = acc[mt * 8 + nt];
            float bx = sBias[col], by = sBias[col + 1];
            if (row < nrows) {
                float2 o;
                o.x = fmaxf(a[0] + bx, 0.f);
                o.y = fmaxf(a[1] + by, 0.f);
                *(float2*)(O + (size_t)row * HD + col) = o;
            }
            if (row + 8 < nrows) {
                float2 o;
                o.x = fmaxf(a[2] + bx, 0.f);
                o.y = fmaxf(a[3] + by, 0.f);
                *(float2*)(O + (size_t)(row + 8) * HD + col) = o;
            }
        }
    }
}

// ---------------------------------------------------------------- pooling
__global__ void zero_pool_kernel() {
    int i = threadIdx.x;
    for (int j = i; j < GG * HD; j += 256) g_sums[j] = 0.f;
    if (i < GG) g_cnt[i] = 0.f;
}
__global__ void pool_kernel(const float* __restrict__ Hf, const int* __restrict__ gid,
                            int nrows) {
    __shared__ float s[GG * HD];
    __shared__ float sc[GG];
    int tid = threadIdx.x;  // 128
    for (int i = tid; i < GG * HD; i += 128) s[i] = 0.f;
    if (tid < GG) sc[tid] = 0.f;
    __syncthreads();
    int start = blockIdx.x * 128;
    int end = min(start + 128, nrows);
    for (int r = start; r < end; r++) {
        int g = __ldg(gid + r);
        s[(g << 7) + tid] += Hf[(size_t)r * HD + tid];
        if (tid == 0) sc[g] += 1.f;
    }
    __syncthreads();
    for (int i = tid; i < GG * HD; i += 128) atomicAdd(&g_sums[i], s[i]);
    if (tid < GG) atomicAdd(&g_cnt[tid], sc[tid]);
}

// ---------------------------------------------------------------- classifier
__global__ void cls_kernel(const float* __restrict__ Wc1, const float* __restrict__ bc1,
                           const float* __restrict__ Wc2, const float* __restrict__ bc2,
                           float* __restrict__ out) {
    __shared__ float hg[GG * HD];
    __shared__ float t1[GG * HD];
    int tid = threadIdx.x;  // 256
    for (int i = tid; i < GG * HD; i += 256) {
        int g = i >> 7;
        hg[i] = g_sums[i] / fmaxf(g_cnt[g], 1.f);
    }
    __syncthreads();
    for (int i = tid; i < GG * HD; i += 256) {
        int g = i >> 7, c = i & 127;
        float a = bc1[c];
        #pragma unroll 8
        for (int k = 0; k < HD; k++) a += hg[(g << 7) + k] * Wc1[k * HD + c];
        t1[i] = fmaxf(a, 0.f);
    }
    __syncthreads();
    for (int i = tid; i < GG * 10; i += 256) {
        int g = i / 10, c = i - g * 10;
        float a = bc2[c];
        #pragma unroll 8
        for (int k = 0; k < HD; k++) a += t1[(g << 7) + k] * Wc2[k * 10 + c];
        out[i] = a;
    }
}

// ---------------------------------------------------------------- launch
extern "C" void kernel_launch(void* const* d_in, const int* in_sizes, int n_in,
                              void* d_out, int out_size) {
    const float* h   = (const float*)d_in[0];
    const int*   src = (const int*)d_in[1];
    const int*   dst = (const int*)d_in[2];
    const int*   gid = (const int*)d_in[3];
    const float* W1a = (const float*)d_in[4];  const float* b1a = (const float*)d_in[5];
    const float* W2a = (const float*)d_in[6];  const float* b2a = (const float*)d_in[7];
    const float* W1b = (const float*)d_in[8];  const float* b1b = (const float*)d_in[9];
    const float* W2b = (const float*)d_in[10]; const float* b2b = (const float*)d_in[11];
    const float* Wc1 = (const float*)d_in[12]; const float* bc1 = (const float*)d_in[13];
    const float* Wc2 = (const float*)d_in[14]; const float* bc2 = (const float*)d_in[15];
    float* out = (float*)d_out;

    int N = in_sizes[0] / HD;
    int E = in_sizes[1];

    float *A, *B, *C;
    __nv_bfloat16 *Wh, *Wl;
    cudaGetSymbolAddress((void**)&A, g_A);
    cudaGetSymbolAddress((void**)&B, g_B);
    cudaGetSymbolAddress((void**)&C, g_C);
    cudaGetSymbolAddress((void**)&Wh, g_Wbh);
    cudaGetSymbolAddress((void**)&Wl, g_Wbl);

    cudaFuncSetAttribute(gemm_mma_kernel, cudaFuncAttributeMaxDynamicSharedMemorySize, SMEM_MMA);

    int nb = (N + 255) / 256;
    int eb = (E + 255) / 256;
    int ab = (N + 7) / 8;
    int gb = (N + 127) / 128;

    // Build CSR (by dst) once; split weights once
    zero_counts_kernel<<<nb, 256>>>(N);
    hist_kernel<<<eb, 256>>>(dst, E);
    wsplit_kernel<<<256, 256>>>(W1a, W2a, W1b, W2b);
    scan_kernel<<<1, 1024>>>(N);
    seed_cursor_kernel<<<nb, 256>>>(N);
    fill_kernel<<<eb, 256>>>(src, dst, E);

    // Layer A
    agg_kernel<<<ab, 256>>>(h, A, N);                                     // A = z1
    gemm_mma_kernel<<<gb, 256, SMEM_MMA>>>(A, Wh + 0 * 16384, Wl + 0 * 16384, b1a, B, N);
    gemm_mma_kernel<<<gb, 256, SMEM_MMA>>>(B, Wh + 1 * 16384, Wl + 1 * 16384, b2a, A, N);
    // Layer B
    agg_kernel<<<ab, 256>>>(A, C, N);                                     // C = z2
    gemm_mma_kernel<<<gb, 256, SMEM_MMA>>>(C, Wh + 2 * 16384, Wl + 2 * 16384, b1b, B, N);
    gemm_mma_kernel<<<gb, 256, SMEM_MMA>>>(B, Wh + 3 * 16384, Wl + 3 * 16384, b2b, A, N);
    // Readout + classifier
    zero_pool_kernel<<<1, 256>>>();
    pool_kernel<<<(N + 127) / 128, 128>>>(A, gid, N);
    cls_kernel<<<1, 256>>>(Wc1, bc1, Wc2, bc2, out);
}

// round 5
// speedup vs baseline: 2.6572x; 1.0901x over previous
#include <cuda_runtime.h>
#include <cuda_bf16.h>
#include <cstdint>

#define NMAX 50048
#define EMAX 800000
#define HD   128
#define GG   16

// Scratch (no cudaMalloc allowed)
__device__ __align__(16) float g_A[NMAX * HD];
__device__ __align__(16) float g_B[NMAX * HD];
__device__ __align__(16) float g_C[NMAX * HD];
__device__ float g_sums[GG * HD];
__device__ float g_cnt[GG];
__device__ int   g_rowptr[NMAX + 1];
__device__ int   g_cursor[NMAX];
__device__ int   g_csr[EMAX];
// decoupled-lookback scan state (reset each call by prep_kernel)
__device__ int   g_bflag[64];
__device__ int   g_bagg[64];
__device__ int   g_bincl[64];
// Pre-split weights, n-major [layer][n][k], bf16 hi/lo
__device__ __align__(16) __nv_bfloat16 g_Wbh[4 * 16384];
__device__ __align__(16) __nv_bfloat16 g_Wbl[4 * 16384];

// ================================================================ prep
// Fused: zero counts (g_cursor), zero scan flags, split weights to bf16 hi/lo.
// W[k][n] row-major -> n-major: g_Wb*[layer][n*128 + k]
__global__ void prep_kernel(const float* __restrict__ W1a, const float* __restrict__ W2a,
                            const float* __restrict__ W1b, const float* __restrict__ W2b,
                            int n) {
    int idx = blockIdx.x * 256 + threadIdx.x;   // 65536 threads
    if (idx < n)  g_cursor[idx] = 0;
    if (idx < 64) g_bflag[idx] = 0;
    int w = idx >> 14, rem = idx & 16383;
    int nn = rem >> 7, k = rem & 127;
    const float* Wp = (w == 0) ? W1a : (w == 1) ? W2a : (w == 2) ? W1b : W2b;
    float v = Wp[k * 128 + nn];
    __nv_bfloat16 hi = __float2bfloat16(v);
    __nv_bfloat16 lo = __float2bfloat16(v - __bfloat162float(hi));
    g_Wbh[idx] = hi;
    g_Wbl[idx] = lo;
}

__global__ void hist_kernel(const int* __restrict__ dst, int nE) {
    int e = blockIdx.x * blockDim.x + threadIdx.x;
    if (e < nE) atomicAdd(&g_cursor[dst[e]], 1);
}

// ---------------- decoupled-lookback scan: counts(g_cursor) -> rowptr + cursor
// 49 blocks x 1024 threads; all blocks co-resident on 148 SMs -> spin is safe.
__global__ void __launch_bounds__(1024) scan_fused_kernel(int n) {
    __shared__ int warpsums[32];
    __shared__ int s_off;
    int tid = threadIdx.x, lane = tid & 31, w = tid >> 5;
    int bid = blockIdx.x;
    int i = bid * 1024 + tid;
    int v = (i < n) ? g_cursor[i] : 0;
    int x = v;
    #pragma unroll
    for (int o = 1; o < 32; o <<= 1) {
        int y = __shfl_up_sync(0xFFFFFFFFu, x, o);
        if (lane >= o) x += y;
    }
    if (lane == 31) warpsums[w] = x;
    __syncthreads();
    if (w == 0) {
        int y = warpsums[lane];
        #pragma unroll
        for (int o = 1; o < 32; o <<= 1) {
            int z = __shfl_up_sync(0xFFFFFFFFu, y, o);
            if (lane >= o) y += z;
        }
        warpsums[lane] = y;
    }
    __syncthreads();
    int incl = x + (w > 0 ? warpsums[w - 1] : 0);
    int total = warpsums[31];

    if (tid == 0) {
        if (bid == 0) {
            g_bincl[0] = total;
            __threadfence();
            atomicExch(&g_bflag[0], 2);
            s_off = 0;
        } else {
            g_bagg[bid] = total;
            __threadfence();
            atomicExch(&g_bflag[bid], 1);
            int run = 0, p = bid - 1;
            while (true) {
                int f;
                do { f = atomicAdd(&g_bflag[p], 0); } while (f == 0);
                if (f == 2) { run += atomicAdd(&g_bincl[p], 0); break; }
                run += atomicAdd(&g_bagg[p], 0);
                p--;
            }
            g_bincl[bid] = run + total;
            __threadfence();
            atomicExch(&g_bflag[bid], 2);
            s_off = run;
        }
    }
    __syncthreads();
    int off = s_off;
    if (i < n) {
        g_rowptr[i + 1] = off + incl;
        g_cursor[i] = off + incl - v;   // exclusive prefix = fill cursor
    }
    if (i == 0) g_rowptr[0] = 0;
}

__global__ void fill_kernel(const int* __restrict__ src, const int* __restrict__ dst, int nE) {
    int e = blockIdx.x * blockDim.x + threadIdx.x;
    if (e < nE) {
        int pos = atomicAdd(&g_cursor[dst[e]], 1);
        g_csr[pos] = src[e];
    }
}

// ------------------------------------------------- CSR gather aggregation
__global__ void __launch_bounds__(256) agg_kernel(const float* __restrict__ H,
                                                  float* __restrict__ Z, int nrows) {
    int warp = threadIdx.x >> 5;
    int lane = threadIdx.x & 31;
    int node = blockIdx.x * 8 + warp;
    if (node >= nrows) return;
    const float4* H4 = (const float4*)H;
    float4 acc = H4[(size_t)node * 32 + lane];
    int beg = g_rowptr[node];
    int end = g_rowptr[node + 1];
    for (int e = beg; e < end; e++) {
        int s = g_csr[e];
        float4 v = H4[(size_t)s * 32 + lane];
        acc.x += v.x; acc.y += v.y; acc.z += v.z; acc.w += v.w;
    }
    ((float4*)Z)[(size_t)node * 32 + lane] = acc;
}

// ================================================================ mma.sync GEMM
// O = relu(Z @ W + b). CTA tile 128x128, K=128. bf16 hi/lo split (3 products).
// smem rows padded to 272B -> fragment loads conflict-free.
#define OFF_AH 0
#define OFF_AL 34816
#define OFF_BH 69632
#define OFF_BL 104448
#define OFF_BIAS 139264
#define SMEM_MMA (139264 + 512)

#define MMA16816(d, a, b0, b1) \
    asm volatile("mma.sync.aligned.m16n8k16.row.col.f32.bf16.bf16.f32 " \
        "{%0,%1,%2,%3}, {%4,%5,%6,%7}, {%8,%9}, {%0,%1,%2,%3};" \
        : "+f"((d)[0]), "+f"((d)[1]), "+f"((d)[2]), "+f"((d)[3]) \
        : "r"((a)[0]), "r"((a)[1]), "r"((a)[2]), "r"((a)[3]), "r"(b0), "r"(b1))

__global__ void __launch_bounds__(256) gemm_mma_kernel(
    const float* __restrict__ Z, const __nv_bfloat16* __restrict__ Wh,
    const __nv_bfloat16* __restrict__ Wl, const float* __restrict__ bias,
    float* __restrict__ O, int nrows)
{
    extern __shared__ char smem[];
    int tid = threadIdx.x, wid = tid >> 5, lane = tid & 31;
    int row0 = blockIdx.x * 128;

    // ---- stage B (copy with repad, 16B chunks) + bias
    {
        const uint4* Bh4 = (const uint4*)Wh;   // 2048 uint4 = 128 rows x 16 chunks
        const uint4* Bl4 = (const uint4*)Wl;
        #pragma unroll
        for (int i = tid; i < 2048; i += 256) {
            int r = i >> 4, c = i & 15;
            *(uint4*)(smem + OFF_BH + r * 272 + c * 16) = Bh4[i];
            *(uint4*)(smem + OFF_BL + r * 272 + c * 16) = Bl4[i];
        }
        if (tid < 128) ((float*)(smem + OFF_BIAS))[tid] = bias[tid];
    }
    // ---- stage A: convert fp32 -> bf16 hi/lo. thread t: row t>>1, half t&1
    {
        int r = tid >> 1, hhalf = tid & 1;
        int row = row0 + r;
        const float4* Zr = (const float4*)(Z + (size_t)row * HD) + hhalf * 16;
        uint32_t* dh = (uint32_t*)(smem + OFF_AH + r * 272 + hhalf * 128);
        uint32_t* dl = (uint32_t*)(smem + OFF_AL + r * 272 + hhalf * 128);
        bool ok = (row < nrows);
        #pragma unroll
        for (int j = 0; j < 16; j++) {
            float4 v = ok ? Zr[j] : make_float4(0.f, 0.f, 0.f, 0.f);
            __nv_bfloat16 hx = __float2bfloat16(v.x), hy = __float2bfloat16(v.y);
            __nv_bfloat16 hz = __float2bfloat16(v.z), hw = __float2bfloat16(v.w);
            __nv_bfloat162 h0 = __nv_bfloat162(hx, hy), h1 = __nv_bfloat162(hz, hw);
            __nv_bfloat162 l0 = __nv_bfloat162(
                __float2bfloat16(v.x - __bfloat162float(hx)),
                __float2bfloat16(v.y - __bfloat162float(hy)));
            __nv_bfloat162 l1 = __nv_bfloat162(
                __float2bfloat16(v.z - __bfloat162float(hz)),
                __float2bfloat16(v.w - __bfloat162float(hw)));
            dh[j * 2 + 0] = *(uint32_t*)&h0;
            dh[j * 2 + 1] = *(uint32_t*)&h1;
            dl[j * 2 + 0] = *(uint32_t*)&l0;
            dl[j * 2 + 1] = *(uint32_t*)&l1;
        }
    }
    __syncthreads();

    // ---- mainloop: warp (wm = wid>>1, wn = wid&1) owns 32 rows x 64 cols
    int wm = wid >> 1, wn = wid & 1;
    int qrow = lane >> 2;            // 0..7
    int qk = (lane & 3) * 2;         // 0,2,4,6

    float acc[16][4];
    #pragma unroll
    for (int i = 0; i < 16; i++) {
        acc[i][0] = 0.f; acc[i][1] = 0.f; acc[i][2] = 0.f; acc[i][3] = 0.f;
    }

    const char* aH = smem + OFF_AH + (size_t)(wm * 32 + qrow) * 272;
    const char* aL = smem + OFF_AL + (size_t)(wm * 32 + qrow) * 272;
    const char* bH = smem + OFF_BH + (size_t)(wn * 64 + qrow) * 272;
    const char* bL = smem + OFF_BL + (size_t)(wn * 64 + qrow) * 272;

    #pragma unroll
    for (int kt = 0; kt < 8; kt++) {
        int kb = (kt * 16 + qk) * 2;   // byte offset within row
        uint32_t ah[2][4], al[2][4];
        #pragma unroll
        for (int mt = 0; mt < 2; mt++) {
            const char* pH = aH + mt * 16 * 272;
            const char* pL = aL + mt * 16 * 272;
            ah[mt][0] = *(const uint32_t*)(pH + kb);
            ah[mt][1] = *(const uint32_t*)(pH + 8 * 272 + kb);
            ah[mt][2] = *(const uint32_t*)(pH + kb + 16);
            ah[mt][3] = *(const uint32_t*)(pH + 8 * 272 + kb + 16);
            al[mt][0] = *(const uint32_t*)(pL + kb);
            al[mt][1] = *(const uint32_t*)(pL + 8 * 272 + kb);
            al[mt][2] = *(const uint32_t*)(pL + kb + 16);
            al[mt][3] = *(const uint32_t*)(pL + 8 * 272 + kb + 16);
        }
        #pragma unroll
        for (int nt = 0; nt < 8; nt++) {
            const char* pBh = bH + nt * 8 * 272;
            const char* pBl = bL + nt * 8 * 272;
            uint32_t bh0 = *(const uint32_t*)(pBh + kb);
            uint32_t bh1 = *(const uint32_t*)(pBh + kb + 16);
            uint32_t bl0 = *(const uint32_t*)(pBl + kb);
            uint32_t bl1 = *(const uint32_t*)(pBl + kb + 16);
            #pragma unroll
            for (int mt = 0; mt < 2; mt++) {
                MMA16816(acc[mt * 8 + nt], ah[mt], bh0, bh1);
                MMA16816(acc[mt * 8 + nt], al[mt], bh0, bh1);
                MMA16816(acc[mt * 8 + nt], ah[mt], bl0, bl1);
            }
        }
    }

    // ---- epilogue: bias + relu, float2 stores
    const float* sBias = (const float*)(smem + OFF_BIAS);
    #pragma unroll
    for (int mt = 0; mt < 2; mt++) {
        #pragma unroll
        for (int nt = 0; nt < 8; nt++) {
            int row = row0 + wm * 32 + mt * 16 + qrow;
            int col = wn * 64 + nt * 8 + qk;
            float* a = acc[mt * 8 + nt];
            float bx = sBias[col], by = sBias[col + 1];
            if (row < nrows) {
                float2 o;
                o.x = fmaxf(a[0] + bx, 0.f);
                o.y = fmaxf(a[1] + by, 0.f);
                *(float2*)(O + (size_t)row * HD + col) = o;
            }
            if (row + 8 < nrows) {
                float2 o;
                o.x = fmaxf(a[2] + bx, 0.f);
                o.y = fmaxf(a[3] + by, 0.f);
                *(float2*)(O + (size_t)(row + 8) * HD + col) = o;
            }
        }
    }
}

// ---------------------------------------------------------------- pooling
__global__ void zero_pool_kernel() {
    int i = threadIdx.x;
    for (int j = i; j < GG * HD; j += 256) g_sums[j] = 0.f;
    if (i < GG) g_cnt[i] = 0.f;
}
__global__ void pool_kernel(const float* __restrict__ Hf, const int* __restrict__ gid,
                            int nrows) {
    __shared__ float s[GG * HD];
    __shared__ float sc[GG];
    int tid = threadIdx.x;  // 128
    for (int i = tid; i < GG * HD; i += 128) s[i] = 0.f;
    if (tid < GG) sc[tid] = 0.f;
    __syncthreads();
    int start = blockIdx.x * 128;
    int end = min(start + 128, nrows);
    for (int r = start; r < end; r++) {
        int g = __ldg(gid + r);
        s[(g << 7) + tid] += Hf[(size_t)r * HD + tid];
        if (tid == 0) sc[g] += 1.f;
    }
    __syncthreads();
    for (int i = tid; i < GG * HD; i += 128) atomicAdd(&g_sums[i], s[i]);
    if (tid < GG) atomicAdd(&g_cnt[tid], sc[tid]);
}

// ---------------------------------------------------------------- classifier
__global__ void cls_kernel(const float* __restrict__ Wc1, const float* __restrict__ bc1,
                           const float* __restrict__ Wc2, const float* __restrict__ bc2,
                           float* __restrict__ out) {
    __shared__ float hg[GG * HD];
    __shared__ float t1[GG * HD];
    int tid = threadIdx.x;  // 256
    for (int i = tid; i < GG * HD; i += 256) {
        int g = i >> 7;
        hg[i] = g_sums[i] / fmaxf(g_cnt[g], 1.f);
    }
    __syncthreads();
    for (int i = tid; i < GG * HD; i += 256) {
        int g = i >> 7, c = i & 127;
        float a = bc1[c];
        #pragma unroll 8
        for (int k = 0; k < HD; k++) a += hg[(g << 7) + k] * Wc1[k * HD + c];
        t1[i] = fmaxf(a, 0.f);
    }
    __syncthreads();
    for (int i = tid; i < GG * 10; i += 256) {
        int g = i / 10, c = i - g * 10;
        float a = bc2[c];
        #pragma unroll 8
        for (int k = 0; k < HD; k++) a += t1[(g << 7) + k] * Wc2[k * 10 + c];
        out[i] = a;
    }
}

// ---------------------------------------------------------------- launch
extern "C" void kernel_launch(void* const* d_in, const int* in_sizes, int n_in,
                              void* d_out, int out_size) {
    const float* h   = (const float*)d_in[0];
    const int*   src = (const int*)d_in[1];
    const int*   dst = (const int*)d_in[2];
    const int*   gid = (const int*)d_in[3];
    const float* W1a = (const float*)d_in[4];  const float* b1a = (const float*)d_in[5];
    const float* W2a = (const float*)d_in[6];  const float* b2a = (const float*)d_in[7];
    const float* W1b = (const float*)d_in[8];  const float* b1b = (const float*)d_in[9];
    const float* W2b = (const float*)d_in[10]; const float* b2b = (const float*)d_in[11];
    const float* Wc1 = (const float*)d_in[12]; const float* bc1 = (const float*)d_in[13];
    const float* Wc2 = (const float*)d_in[14]; const float* bc2 = (const float*)d_in[15];
    float* out = (float*)d_out;

    int N = in_sizes[0] / HD;
    int E = in_sizes[1];

    float *A, *B, *C;
    __nv_bfloat16 *Wh, *Wl;
    cudaGetSymbolAddress((void**)&A, g_A);
    cudaGetSymbolAddress((void**)&B, g_B);
    cudaGetSymbolAddress((void**)&C, g_C);
    cudaGetSymbolAddress((void**)&Wh, g_Wbh);
    cudaGetSymbolAddress((void**)&Wl, g_Wbl);

    cudaFuncSetAttribute(gemm_mma_kernel, cudaFuncAttributeMaxDynamicSharedMemorySize, SMEM_MMA);

    int eb = (E + 255) / 256;
    int ab = (N + 7) / 8;
    int gb = (N + 127) / 128;
    int sb = (N + 1023) / 1024;   // 49 blocks, all co-resident

    // Build CSR (by dst) + split weights
    prep_kernel<<<256, 256>>>(W1a, W2a, W1b, W2b, N);       // 0
    hist_kernel<<<eb, 256>>>(dst, E);                       // 1
    scan_fused_kernel<<<sb, 1024>>>(N);                     // 2  rowptr + cursor
    fill_kernel<<<eb, 256>>>(src, dst, E);                  // 3

    // Layer A
    agg_kernel<<<ab, 256>>>(h, A, N);                       // 4  A = z1
    gemm_mma_kernel<<<gb, 256, SMEM_MMA>>>(A, Wh + 0 * 16384, Wl + 0 * 16384, b1a, B, N);  // 5 (ncu)
    gemm_mma_kernel<<<gb, 256, SMEM_MMA>>>(B, Wh + 1 * 16384, Wl + 1 * 16384, b2a, A, N);
    // Layer B
    agg_kernel<<<ab, 256>>>(A, C, N);                       // C = z2
    gemm_mma_kernel<<<gb, 256, SMEM_MMA>>>(C, Wh + 2 * 16384, Wl + 2 * 16384, b1b, B, N);
    gemm_mma_kernel<<<gb, 256, SMEM_MMA>>>(B, Wh + 3 * 16384, Wl + 3 * 16384, b2b, A, N);
    // Readout + classifier
    zero_pool_kernel<<<1, 256>>>();
    pool_kernel<<<(N + 127) / 128, 128>>>(A, gid, N);
    cls_kernel<<<1, 256>>>(Wc1, bc1, Wc2, bc2, out);
}

// round 6
// speedup vs baseline: 2.8674x; 1.0791x over previous
#include <cuda_runtime.h>
#include <cuda_bf16.h>
#include <cstdint>

#define NMAX 50048
#define EMAX 800000
#define HD   128
#define GG   16

// Scratch (no cudaMalloc allowed)
__device__ __align__(16) float g_A[NMAX * HD];                 // fp32 h1 / h2
__device__ __align__(16) __nv_bfloat16 g_Zh[NMAX * HD];        // z split hi
__device__ __align__(16) __nv_bfloat16 g_Zl[NMAX * HD];        // z split lo
__device__ __align__(16) __nv_bfloat16 g_Th[NMAX * HD];        // mid split hi
__device__ __align__(16) __nv_bfloat16 g_Tl[NMAX * HD];        // mid split lo
__device__ float g_sums[GG * HD];
__device__ float g_cnt[GG];
__device__ int   g_rowptr[NMAX + 1];
__device__ int   g_cursor[NMAX];
__device__ int   g_csr[EMAX];
__device__ int   g_bflag[64];
__device__ int   g_bagg[64];
__device__ int   g_bincl[64];
// Pre-split weights, n-major [layer][n][k], bf16 hi/lo
__device__ __align__(16) __nv_bfloat16 g_Wbh[4 * 16384];
__device__ __align__(16) __nv_bfloat16 g_Wbl[4 * 16384];

// ================================================================ prep
// Fused: zero counts + scan flags + pool accumulators, split weights.
__global__ void prep_kernel(const float* __restrict__ W1a, const float* __restrict__ W2a,
                            const float* __restrict__ W1b, const float* __restrict__ W2b,
                            int n) {
    int idx = blockIdx.x * 256 + threadIdx.x;   // 65536 threads
    if (idx < n)  g_cursor[idx] = 0;
    if (idx < 64) g_bflag[idx] = 0;
    if (idx < GG * HD) g_sums[idx] = 0.f;
    if (idx < GG) g_cnt[idx] = 0.f;
    int w = idx >> 14, rem = idx & 16383;
    int nn = rem >> 7, k = rem & 127;
    const float* Wp = (w == 0) ? W1a : (w == 1) ? W2a : (w == 2) ? W1b : W2b;
    float v = Wp[k * 128 + nn];
    __nv_bfloat16 hi = __float2bfloat16(v);
    __nv_bfloat16 lo = __float2bfloat16(v - __bfloat162float(hi));
    g_Wbh[idx] = hi;
    g_Wbl[idx] = lo;
}

// 4 edges per thread, independent RED ops
__global__ void hist_kernel(const int* __restrict__ dst, int nE) {
    int base = (blockIdx.x * blockDim.x + threadIdx.x) * 4;
    if (base + 3 < nE) {
        int4 d = *(const int4*)(dst + base);
        atomicAdd(&g_cursor[d.x], 1);
        atomicAdd(&g_cursor[d.y], 1);
        atomicAdd(&g_cursor[d.z], 1);
        atomicAdd(&g_cursor[d.w], 1);
    } else {
        for (int e = base; e < nE; e++) atomicAdd(&g_cursor[dst[e]], 1);
    }
}

// ---------------- decoupled-lookback scan: counts -> rowptr + cursor
__global__ void __launch_bounds__(1024) scan_fused_kernel(int n) {
    __shared__ int warpsums[32];
    __shared__ int s_off;
    int tid = threadIdx.x, lane = tid & 31, w = tid >> 5;
    int bid = blockIdx.x;
    int i = bid * 1024 + tid;
    int v = (i < n) ? g_cursor[i] : 0;
    int x = v;
    #pragma unroll
    for (int o = 1; o < 32; o <<= 1) {
        int y = __shfl_up_sync(0xFFFFFFFFu, x, o);
        if (lane >= o) x += y;
    }
    if (lane == 31) warpsums[w] = x;
    __syncthreads();
    if (w == 0) {
        int y = warpsums[lane];
        #pragma unroll
        for (int o = 1; o < 32; o <<= 1) {
            int z = __shfl_up_sync(0xFFFFFFFFu, y, o);
            if (lane >= o) y += z;
        }
        warpsums[lane] = y;
    }
    __syncthreads();
    int incl = x + (w > 0 ? warpsums[w - 1] : 0);
    int total = warpsums[31];

    if (tid == 0) {
        if (bid == 0) {
            g_bincl[0] = total;
            __threadfence();
            atomicExch(&g_bflag[0], 2);
            s_off = 0;
        } else {
            g_bagg[bid] = total;
            __threadfence();
            atomicExch(&g_bflag[bid], 1);
            int run = 0, p = bid - 1;
            while (true) {
                int f;
                do { f = atomicAdd(&g_bflag[p], 0); } while (f == 0);
                if (f == 2) { run += atomicAdd(&g_bincl[p], 0); break; }
                run += atomicAdd(&g_bagg[p], 0);
                p--;
            }
            g_bincl[bid] = run + total;
            __threadfence();
            atomicExch(&g_bflag[bid], 2);
            s_off = run;
        }
    }
    __syncthreads();
    int off = s_off;
    if (i < n) {
        g_rowptr[i + 1] = off + incl;
        g_cursor[i] = off + incl - v;
    }
    if (i == 0) g_rowptr[0] = 0;
}

// 4 edges per thread -> 4 atomics in flight
__global__ void fill_kernel(const int* __restrict__ src, const int* __restrict__ dst, int nE) {
    int base = (blockIdx.x * blockDim.x + threadIdx.x) * 4;
    if (base + 3 < nE) {
        int4 d = *(const int4*)(dst + base);
        int4 s = *(const int4*)(src + base);
        int p0 = atomicAdd(&g_cursor[d.x], 1);
        int p1 = atomicAdd(&g_cursor[d.y], 1);
        int p2 = atomicAdd(&g_cursor[d.z], 1);
        int p3 = atomicAdd(&g_cursor[d.w], 1);
        g_csr[p0] = s.x; g_csr[p1] = s.y; g_csr[p2] = s.z; g_csr[p3] = s.w;
    } else {
        for (int e = base; e < nE; e++) {
            int pos = atomicAdd(&g_cursor[dst[e]], 1);
            g_csr[pos] = src[e];
        }
    }
}

// ------------------------------------------------- CSR gather aggregation
// fp32 input, split bf16 hi/lo output (z feeds GEMM only)
__global__ void __launch_bounds__(256) agg_kernel(const float* __restrict__ H,
                                                  __nv_bfloat16* __restrict__ Zh,
                                                  __nv_bfloat16* __restrict__ Zl,
                                                  int nrows) {
    int warp = threadIdx.x >> 5;
    int lane = threadIdx.x & 31;
    int node = blockIdx.x * 8 + warp;
    if (node >= nrows) return;
    const float4* H4 = (const float4*)H;
    float4 acc = H4[(size_t)node * 32 + lane];
    int beg = g_rowptr[node];
    int end = g_rowptr[node + 1];
    for (int e = beg; e < end; e++) {
        int s = g_csr[e];
        float4 v = H4[(size_t)s * 32 + lane];
        acc.x += v.x; acc.y += v.y; acc.z += v.z; acc.w += v.w;
    }
    // split: 4 floats -> 2x bf16x2 hi + 2x bf16x2 lo
    __nv_bfloat16 hx = __float2bfloat16(acc.x), hy = __float2bfloat16(acc.y);
    __nv_bfloat16 hz = __float2bfloat16(acc.z), hw = __float2bfloat16(acc.w);
    __nv_bfloat162 h0(hx, hy), h1(hz, hw);
    __nv_bfloat162 l0(__float2bfloat16(acc.x - __bfloat162float(hx)),
                      __float2bfloat16(acc.y - __bfloat162float(hy)));
    __nv_bfloat162 l1(__float2bfloat16(acc.z - __bfloat162float(hz)),
                      __float2bfloat16(acc.w - __bfloat162float(hw)));
    uint2 ph = make_uint2(*(uint32_t*)&h0, *(uint32_t*)&h1);
    uint2 pl = make_uint2(*(uint32_t*)&l0, *(uint32_t*)&l1);
    ((uint2*)(Zh + (size_t)node * HD))[lane] = ph;
    ((uint2*)(Zl + (size_t)node * HD))[lane] = pl;
}

// ================================================================ mma.sync GEMM
// Input A pre-split (hi/lo bf16 planes). CTA tile 128x128, K=128, 3-product split.
#define OFF_AH 0
#define OFF_AL 34816
#define OFF_BH 69632
#define OFF_BL 104448
#define OFF_BIAS 139264
#define SMEM_MMA (139264 + 512)

#define MMA16816(d, a, b0, b1) \
    asm volatile("mma.sync.aligned.m16n8k16.row.col.f32.bf16.bf16.f32 " \
        "{%0,%1,%2,%3}, {%4,%5,%6,%7}, {%8,%9}, {%0,%1,%2,%3};" \
        : "+f"((d)[0]), "+f"((d)[1]), "+f"((d)[2]), "+f"((d)[3]) \
        : "r"((a)[0]), "r"((a)[1]), "r"((a)[2]), "r"((a)[3]), "r"(b0), "r"(b1))

template<bool SPLIT_OUT>
__global__ void __launch_bounds__(256) gemm_mma_kernel(
    const __nv_bfloat16* __restrict__ Ah, const __nv_bfloat16* __restrict__ Al,
    const __nv_bfloat16* __restrict__ Wh, const __nv_bfloat16* __restrict__ Wl,
    const float* __restrict__ bias,
    float* __restrict__ O, __nv_bfloat16* __restrict__ Oh,
    __nv_bfloat16* __restrict__ Ol, int nrows)
{
    extern __shared__ char smem[];
    int tid = threadIdx.x, wid = tid >> 5, lane = tid & 31;
    int row0 = blockIdx.x * 128;

    // ---- stage B + bias + A (all pure uint4 copies, repad to 272B rows)
    {
        const uint4* Bh4 = (const uint4*)Wh;
        const uint4* Bl4 = (const uint4*)Wl;
        const uint4* Ah4 = (const uint4*)Ah + (size_t)row0 * 16;
        const uint4* Al4 = (const uint4*)Al + (size_t)row0 * 16;
        #pragma unroll
        for (int i = tid; i < 2048; i += 256) {
            int r = i >> 4, c = i & 15;
            *(uint4*)(smem + OFF_BH + r * 272 + c * 16) = Bh4[i];
            *(uint4*)(smem + OFF_BL + r * 272 + c * 16) = Bl4[i];
            *(uint4*)(smem + OFF_AH + r * 272 + c * 16) = Ah4[i];
            *(uint4*)(smem + OFF_AL + r * 272 + c * 16) = Al4[i];
        }
        if (tid < 128) ((float*)(smem + OFF_BIAS))[tid] = bias[tid];
    }
    __syncthreads();

    // ---- mainloop: warp (wm = wid>>1, wn = wid&1) owns 32 rows x 64 cols
    int wm = wid >> 1, wn = wid & 1;
    int qrow = lane >> 2;
    int qk = (lane & 3) * 2;

    float acc[16][4];
    #pragma unroll
    for (int i = 0; i < 16; i++) {
        acc[i][0] = 0.f; acc[i][1] = 0.f; acc[i][2] = 0.f; acc[i][3] = 0.f;
    }

    const char* aH = smem + OFF_AH + (size_t)(wm * 32 + qrow) * 272;
    const char* aL = smem + OFF_AL + (size_t)(wm * 32 + qrow) * 272;
    const char* bH = smem + OFF_BH + (size_t)(wn * 64 + qrow) * 272;
    const char* bL = smem + OFF_BL + (size_t)(wn * 64 + qrow) * 272;

    #pragma unroll
    for (int kt = 0; kt < 8; kt++) {
        int kb = (kt * 16 + qk) * 2;
        uint32_t ah[2][4], al[2][4];
        #pragma unroll
        for (int mt = 0; mt < 2; mt++) {
            const char* pH = aH + mt * 16 * 272;
            const char* pL = aL + mt * 16 * 272;
            ah[mt][0] = *(const uint32_t*)(pH + kb);
            ah[mt][1] = *(const uint32_t*)(pH + 8 * 272 + kb);
            ah[mt][2] = *(const uint32_t*)(pH + kb + 16);
            ah[mt][3] = *(const uint32_t*)(pH + 8 * 272 + kb + 16);
            al[mt][0] = *(const uint32_t*)(pL + kb);
            al[mt][1] = *(const uint32_t*)(pL + 8 * 272 + kb);
            al[mt][2] = *(const uint32_t*)(pL + kb + 16);
            al[mt][3] = *(const uint32_t*)(pL + 8 * 272 + kb + 16);
        }
        #pragma unroll
        for (int nt = 0; nt < 8; nt++) {
            const char* pBh = bH + nt * 8 * 272;
            const char* pBl = bL + nt * 8 * 272;
            uint32_t bh0 = *(const uint32_t*)(pBh + kb);
            uint32_t bh1 = *(const uint32_t*)(pBh + kb + 16);
            uint32_t bl0 = *(const uint32_t*)(pBl + kb);
            uint32_t bl1 = *(const uint32_t*)(pBl + kb + 16);
            #pragma unroll
            for (int mt = 0; mt < 2; mt++) {
                MMA16816(acc[mt * 8 + nt], ah[mt], bh0, bh1);
                MMA16816(acc[mt * 8 + nt], al[mt], bh0, bh1);
                MMA16816(acc[mt * 8 + nt], ah[mt], bl0, bl1);
            }
        }
    }

    // ---- epilogue: bias + relu; fp32 store or split bf16 hi/lo store
    const float* sBias = (const float*)(smem + OFF_BIAS);
    #pragma unroll
    for (int mt = 0; mt < 2; mt++) {
        #pragma unroll
        for (int nt = 0; nt < 8; nt++) {
            int row = row0 + wm * 32 + mt * 16 + qrow;
            int col = wn * 64 + nt * 8 + qk;
            float* a = acc[mt * 8 + nt];
            float bx = sBias[col], by = sBias[col + 1];
            #pragma unroll
            for (int half = 0; half < 2; half++) {
                int rr = row + half * 8;
                if (rr < nrows) {
                    float ox = fmaxf(a[half * 2 + 0] + bx, 0.f);
                    float oy = fmaxf(a[half * 2 + 1] + by, 0.f);
                    if (SPLIT_OUT) {
                        __nv_bfloat16 hx = __float2bfloat16(ox);
                        __nv_bfloat16 hy = __float2bfloat16(oy);
                        __nv_bfloat162 hp(hx, hy);
                        __nv_bfloat162 lp(__float2bfloat16(ox - __bfloat162float(hx)),
                                          __float2bfloat16(oy - __bfloat162float(hy)));
                        *(uint32_t*)(Oh + (size_t)rr * HD + col) = *(uint32_t*)&hp;
                        *(uint32_t*)(Ol + (size_t)rr * HD + col) = *(uint32_t*)&lp;
                    } else {
                        float2 o; o.x = ox; o.y = oy;
                        *(float2*)(O + (size_t)rr * HD + col) = o;
                    }
                }
            }
        }
    }
}

// ---------------------------------------------------------------- pooling
__global__ void pool_kernel(const float* __restrict__ Hf, const int* __restrict__ gid,
                            int nrows) {
    __shared__ float s[GG * HD];
    __shared__ float sc[GG];
    int tid = threadIdx.x;  // 128
    for (int i = tid; i < GG * HD; i += 128) s[i] = 0.f;
    if (tid < GG) sc[tid] = 0.f;
    __syncthreads();
    int start = blockIdx.x * 128;
    int end = min(start + 128, nrows);
    for (int r = start; r < end; r++) {
        int g = __ldg(gid + r);
        s[(g << 7) + tid] += Hf[(size_t)r * HD + tid];
        if (tid == 0) sc[g] += 1.f;
    }
    __syncthreads();
    for (int i = tid; i < GG * HD; i += 128) atomicAdd(&g_sums[i], s[i]);
    if (tid < GG) atomicAdd(&g_cnt[tid], sc[tid]);
}

// ---------------------------------------------------------------- classifier
__global__ void cls_kernel(const float* __restrict__ Wc1, const float* __restrict__ bc1,
                           const float* __restrict__ Wc2, const float* __restrict__ bc2,
                           float* __restrict__ out) {
    __shared__ float hg[GG * HD];
    __shared__ float t1[GG * HD];
    int tid = threadIdx.x;  // 256
    for (int i = tid; i < GG * HD; i += 256) {
        int g = i >> 7;
        hg[i] = g_sums[i] / fmaxf(g_cnt[g], 1.f);
    }
    __syncthreads();
    for (int i = tid; i < GG * HD; i += 256) {
        int g = i >> 7, c = i & 127;
        float a = bc1[c];
        #pragma unroll 8
        for (int k = 0; k < HD; k++) a += hg[(g << 7) + k] * Wc1[k * HD + c];
        t1[i] = fmaxf(a, 0.f);
    }
    __syncthreads();
    for (int i = tid; i < GG * 10; i += 256) {
        int g = i / 10, c = i - g * 10;
        float a = bc2[c];
        #pragma unroll 8
        for (int k = 0; k < HD; k++) a += t1[(g << 7) + k] * Wc2[k * 10 + c];
        out[i] = a;
    }
}

// ---------------------------------------------------------------- launch
extern "C" void kernel_launch(void* const* d_in, const int* in_sizes, int n_in,
                              void* d_out, int out_size) {
    const float* h   = (const float*)d_in[0];
    const int*   src = (const int*)d_in[1];
    const int*   dst = (const int*)d_in[2];
    const int*   gid = (const int*)d_in[3];
    const float* W1a = (const float*)d_in[4];  const float* b1a = (const float*)d_in[5];
    const float* W2a = (const float*)d_in[6];  const float* b2a = (const float*)d_in[7];
    const float* W1b = (const float*)d_in[8];  const float* b1b = (const float*)d_in[9];
    const float* W2b = (const float*)d_in[10]; const float* b2b = (const float*)d_in[11];
    const float* Wc1 = (const float*)d_in[12]; const float* bc1 = (const float*)d_in[13];
    const float* Wc2 = (const float*)d_in[14]; const float* bc2 = (const float*)d_in[15];
    float* out = (float*)d_out;

    int N = in_sizes[0] / HD;
    int E = in_sizes[1];

    float* A;
    __nv_bfloat16 *Zh, *Zl, *Th, *Tl, *Wh, *Wl;
    cudaGetSymbolAddress((void**)&A, g_A);
    cudaGetSymbolAddress((void**)&Zh, g_Zh);
    cudaGetSymbolAddress((void**)&Zl, g_Zl);
    cudaGetSymbolAddress((void**)&Th, g_Th);
    cudaGetSymbolAddress((void**)&Tl, g_Tl);
    cudaGetSymbolAddress((void**)&Wh, g_Wbh);
    cudaGetSymbolAddress((void**)&Wl, g_Wbl);

    cudaFuncSetAttribute(gemm_mma_kernel<true>,
                         cudaFuncAttributeMaxDynamicSharedMemorySize, SMEM_MMA);
    cudaFuncSetAttribute(gemm_mma_kernel<false>,
                         cudaFuncAttributeMaxDynamicSharedMemorySize, SMEM_MMA);

    int eb4 = ((E + 3) / 4 + 255) / 256;
    int ab = (N + 7) / 8;
    int gb = (N + 127) / 128;
    int sb = (N + 1023) / 1024;

    // CSR build + weight split
    prep_kernel<<<256, 256>>>(W1a, W2a, W1b, W2b, N);
    hist_kernel<<<eb4, 256>>>(dst, E);
    scan_fused_kernel<<<sb, 1024>>>(N);
    fill_kernel<<<eb4, 256>>>(src, dst, E);

    // Layer A
    agg_kernel<<<ab, 256>>>(h, Zh, Zl, N);                                        // z1 split
    gemm_mma_kernel<true><<<gb, 256, SMEM_MMA>>>(Zh, Zl, Wh + 0 * 16384, Wl + 0 * 16384,
                                                 b1a, nullptr, Th, Tl, N);
    gemm_mma_kernel<false><<<gb, 256, SMEM_MMA>>>(Th, Tl, Wh + 1 * 16384, Wl + 1 * 16384,
                                                  b2a, A, nullptr, nullptr, N);   // h1 fp32
    // Layer B
    agg_kernel<<<ab, 256>>>(A, Zh, Zl, N);                                        // z2 split
    gemm_mma_kernel<true><<<gb, 256, SMEM_MMA>>>(Zh, Zl, Wh + 2 * 16384, Wl + 2 * 16384,
                                                 b1b, nullptr, Th, Tl, N);
    gemm_mma_kernel<false><<<gb, 256, SMEM_MMA>>>(Th, Tl, Wh + 3 * 16384, Wl + 3 * 16384,
                                                  b2b, A, nullptr, nullptr, N);   // h2 fp32
    // Readout + classifier
    pool_kernel<<<(N + 127) / 128, 128>>>(A, gid, N);
    cls_kernel<<<1, 256>>>(Wc1, bc1, Wc2, bc2, out);
}